// round 2
// baseline (speedup 1.0000x reference)
#include <cuda_runtime.h>
#include <math.h>

#define BATCH 128
#define SEQ   512
#define EMB   512
#define HID   512
#define G4    2048
#define NQ    8
#define TAGS  50
#define NB2   128   // persistent recurrence blocks (<= SM count, guaranteed co-resident)

// ---------------- device scratch (no allocations allowed) ----------------
__device__ float    g_Z[(size_t)SEQ * G4 * BATCH];  // [t][j][b]  512 MB
__device__ float    g_h[2][HID][BATCH];             // double-buffered hidden state [k][b]
__device__ unsigned g_bar;

// ---------------- kernel 1: Zx = x @ Wih^T + (bih + bhh) ----------------
// grid (16, 512): blockIdx.y = t, blockIdx.x = 128-wide j tile. 256 thr, 8x8 reg tile.
__global__ void __launch_bounds__(256) gates_gemm(const float* __restrict__ x,
                                                  const float* __restrict__ Wih,
                                                  const float* __restrict__ bih,
                                                  const float* __restrict__ bhh)
{
    const int t  = blockIdx.y;
    const int j0 = blockIdx.x * 128;
    __shared__ float xs[32][BATCH + 4];
    __shared__ float ws[32][128 + 4];
    const int tid = threadIdx.x;
    const int tx = tid & 15;   // j group (8 cols each)
    const int ty = tid >> 4;   // b group (8 rows each)

    float acc[8][8];
#pragma unroll
    for (int i = 0; i < 8; i++)
#pragma unroll
        for (int j = 0; j < 8; j++) acc[i][j] = 0.f;

    for (int e0 = 0; e0 < EMB; e0 += 32) {
#pragma unroll
        for (int i = 0; i < 4; i++) {            // x chunk -> xs[e][b]
            int lid = tid + i * 256;             // 0..1023
            int b   = lid >> 3;
            int ev  = lid & 7;
            float4 v = *(const float4*)&x[(size_t)b * (SEQ * EMB) + (size_t)t * EMB + e0 + ev * 4];
            xs[ev * 4 + 0][b] = v.x; xs[ev * 4 + 1][b] = v.y;
            xs[ev * 4 + 2][b] = v.z; xs[ev * 4 + 3][b] = v.w;
        }
#pragma unroll
        for (int i = 0; i < 4; i++) {            // Wih chunk -> ws[e][j]
            int lid = tid + i * 256;
            int jj  = lid >> 3;
            int ev  = lid & 7;
            float4 v = *(const float4*)&Wih[(size_t)(j0 + jj) * EMB + e0 + ev * 4];
            ws[ev * 4 + 0][jj] = v.x; ws[ev * 4 + 1][jj] = v.y;
            ws[ev * 4 + 2][jj] = v.z; ws[ev * 4 + 3][jj] = v.w;
        }
        __syncthreads();
#pragma unroll
        for (int e = 0; e < 32; e++) {
            float wr[8], hr[8];
#pragma unroll
            for (int u = 0; u < 8; u++) wr[u] = ws[e][tx * 8 + u];
#pragma unroll
            for (int u = 0; u < 8; u++) hr[u] = xs[e][ty * 8 + u];
#pragma unroll
            for (int jj = 0; jj < 8; jj++)
#pragma unroll
                for (int bb = 0; bb < 8; bb++)
                    acc[jj][bb] = fmaf(wr[jj], hr[bb], acc[jj][bb]);
        }
        __syncthreads();
    }
#pragma unroll
    for (int jj = 0; jj < 8; jj++) {
        int j = j0 + tx * 8 + jj;
        float bsum = bih[j] + bhh[j];
        float* dst = &g_Z[((size_t)t * G4 + j) * BATCH + ty * 8];
#pragma unroll
        for (int bb = 0; bb < 8; bb += 4) {
            float4 v;
            v.x = acc[jj][bb + 0] + bsum; v.y = acc[jj][bb + 1] + bsum;
            v.z = acc[jj][bb + 2] + bsum; v.w = acc[jj][bb + 3] + bsum;
            *(float4*)&dst[bb] = v;
        }
    }
}

// ---------------- kernel 2: persistent LSTM recurrence ----------------
__global__ void __launch_bounds__(32) bar_init() { if (threadIdx.x == 0) g_bar = 0u; }

__device__ __forceinline__ float sigf(float v) { return 1.f / (1.f + expf(-v)); }

__device__ __forceinline__ void grid_bar(unsigned round)
{
    __threadfence();
    __syncthreads();
    if (threadIdx.x == 0) {
        atomicAdd(&g_bar, 1u);
        const unsigned target = round * NB2;
        while (atomicAdd(&g_bar, 0u) < target) { }
    }
    __syncthreads();
}

// 128 blocks x 256 threads. Block bk owns hidden units k0..k0+3 across all 4 gates
// (16 output columns), all 128 batch rows. Whh slice cached in SMEM for all steps.
__global__ void __launch_bounds__(256) lstm_rec(const float* __restrict__ Whh)
{
    const int bk  = blockIdx.x;
    const int k0  = bk * 4;
    const int tid = threadIdx.x;
    __shared__ float ws[HID][16];      // [k][cj]  cj = gate*4 + jj   (32 KB)
    __shared__ float zbuf[16][BATCH];  // gate pre-activations          (8 KB)
    __shared__ float cs[4][BATCH];     // private cell state            (2 KB)

    for (int idx = tid; idx < HID * 16; idx += 256) {
        int k = idx >> 4, cj = idx & 15;
        int gate = cj >> 2, jj = cj & 3;
        ws[k][cj] = Whh[(size_t)(gate * HID + k0 + jj) * HID + k];
    }
    for (int e = tid; e < 4 * BATCH; e += 256) {
        int jj = e >> 7, b = e & 127;
        cs[jj][b] = 0.f;
        g_h[0][k0 + jj][b] = 0.f;
    }
    grid_bar(1);   // all h zeroed before step 0 reads

    const int tx = tid & 7;       // column pair: cols tx*2, tx*2+1
    const int ty = tid >> 3;      // batch group: b0 = ty*4
    const int b0 = ty * 4;
    int p = 0;

    for (int t = 0; t < SEQ; t++) {
        float acc[4][2];
#pragma unroll
        for (int i = 0; i < 4; i++) { acc[i][0] = 0.f; acc[i][1] = 0.f; }
        const float* hb = &g_h[p][0][0];
#pragma unroll 8
        for (int k = 0; k < HID; k++) {
            const float4 h4 = __ldcg(reinterpret_cast<const float4*>(hb + (size_t)k * BATCH + b0));
            const float w0 = ws[k][tx * 2 + 0];
            const float w1 = ws[k][tx * 2 + 1];
            acc[0][0] = fmaf(h4.x, w0, acc[0][0]); acc[0][1] = fmaf(h4.x, w1, acc[0][1]);
            acc[1][0] = fmaf(h4.y, w0, acc[1][0]); acc[1][1] = fmaf(h4.y, w1, acc[1][1]);
            acc[2][0] = fmaf(h4.z, w0, acc[2][0]); acc[2][1] = fmaf(h4.z, w1, acc[2][1]);
            acc[3][0] = fmaf(h4.w, w0, acc[3][0]); acc[3][1] = fmaf(h4.w, w1, acc[3][1]);
        }
#pragma unroll
        for (int cc = 0; cc < 2; cc++) {
            int cj = tx * 2 + cc;
            int j  = (cj >> 2) * HID + k0 + (cj & 3);
            float4 z4 = *(const float4*)&g_Z[((size_t)t * G4 + j) * BATCH + b0];
            zbuf[cj][b0 + 0] = acc[0][cc] + z4.x;
            zbuf[cj][b0 + 1] = acc[1][cc] + z4.y;
            zbuf[cj][b0 + 2] = acc[2][cc] + z4.z;
            zbuf[cj][b0 + 3] = acc[3][cc] + z4.w;
        }
        __syncthreads();
        for (int e = tid; e < 4 * BATCH; e += 256) {
            int jj = e >> 7, b = e & 127;
            float zi = zbuf[0 * 4 + jj][b];
            float zf = zbuf[1 * 4 + jj][b];
            float zg = zbuf[2 * 4 + jj][b];
            float zo = zbuf[3 * 4 + jj][b];
            float c  = sigf(zf) * cs[jj][b] + sigf(zi) * tanhf(zg);
            cs[jj][b] = c;
            __stcg(&g_h[p ^ 1][k0 + jj][b], sigf(zo) * tanhf(c));
        }
        p ^= 1;
        grid_bar((unsigned)t + 2);
    }
}

// ---------------- kernel 3: quantum gates + logits + log_softmax ----------------
__global__ void __launch_bounds__(256) tail_kernel(const float* __restrict__ Wf, const float* __restrict__ bf,
                                                   const float* __restrict__ Wu, const float* __restrict__ bu,
                                                   const float* __restrict__ Wo, const float* __restrict__ bo,
                                                   const float* __restrict__ thf, const float* __restrict__ thu,
                                                   const float* __restrict__ tho,
                                                   const float* __restrict__ Wt, const float* __restrict__ bt,
                                                   float* __restrict__ out)
{
    const int b = blockIdx.x;
    const int warp = threadIdx.x >> 5, lane = threadIdx.x & 31;
    __shared__ float v[3][NQ];
    __shared__ float ho[NQ];
    __shared__ float lg[TAGS];
    __shared__ float red[2];

    // 3 gates x 8 qubit dots of length 512; q = warp id
    for (int r = 0; r < 3; r++) {
        const float* W = (r == 0) ? Wf : ((r == 1) ? Wu : Wo);
        float s = 0.f;
        for (int k = lane; k < HID; k += 32)
            s += g_h[0][k][b] * W[warp * HID + k];
#pragma unroll
        for (int o = 16; o; o >>= 1) s += __shfl_xor_sync(0xFFFFFFFFu, s, o);
        if (lane == 0) v[r][warp] = s;
    }
    __syncthreads();
    if (threadIdx.x < NQ) {
        int q = threadIdx.x;
        float fv = sigf(cosf(v[0][q] + bf[q] + thf[q]));
        float gv = tanhf(cosf(v[1][q] + bu[q] + thu[q]));
        float ov = sigf(cosf(v[2][q] + bo[q] + tho[q]));
        ho[q] = ov * tanhf(fv * gv);
    }
    __syncthreads();
    if (threadIdx.x < TAGS) {
        float s = bt[threadIdx.x];
#pragma unroll
        for (int q = 0; q < NQ; q++) s += ho[q] * Wt[threadIdx.x * NQ + q];
        lg[threadIdx.x] = s;
    }
    __syncthreads();
    if (threadIdx.x == 0) {
        float m = -1e30f;
        for (int i = 0; i < TAGS; i++) m = fmaxf(m, lg[i]);
        float se = 0.f;
        for (int i = 0; i < TAGS; i++) se += expf(lg[i] - m);
        red[0] = m; red[1] = logf(se);
    }
    __syncthreads();
    if (threadIdx.x < TAGS)
        out[(size_t)b * TAGS + threadIdx.x] = lg[threadIdx.x] - red[0] - red[1];
}

// ---------------- launch ----------------
extern "C" void kernel_launch(void* const* d_in, const int* in_sizes, int n_in,
                              void* d_out, int out_size)
{
    const float* x   = (const float*)d_in[0];
    const float* Wih = (const float*)d_in[1];
    const float* Whh = (const float*)d_in[2];
    const float* bih = (const float*)d_in[3];
    const float* bhh = (const float*)d_in[4];
    const float* Wf  = (const float*)d_in[5];
    const float* bf  = (const float*)d_in[6];
    /* d_in[7], d_in[8] = Wi, bi : computed-but-unused in reference */
    const float* Wu  = (const float*)d_in[9];
    const float* bu  = (const float*)d_in[10];
    const float* Wo  = (const float*)d_in[11];
    const float* bo  = (const float*)d_in[12];
    const float* thf = (const float*)d_in[13];
    /* d_in[14] = thi : unused */
    const float* thu = (const float*)d_in[15];
    const float* tho = (const float*)d_in[16];
    const float* Wt  = (const float*)d_in[17];
    const float* bt  = (const float*)d_in[18];
    float* out = (float*)d_out;

    dim3 g1(16, 512);
    gates_gemm<<<g1, 256>>>(x, Wih, bih, bhh);
    bar_init<<<1, 32>>>();
    lstm_rec<<<NB2, 256>>>(Whh);
    tail_kernel<<<BATCH, 256>>>(Wf, bf, Wu, bu, Wo, bo, thf, thu, tho, Wt, bt, out);
}